// round 8
// baseline (speedup 1.0000x reference)
#include <cuda_runtime.h>
#include <cuda_fp16.h>
#include <cstdint>

// CIN via mma.sync (base-ISA tensor cores).
// out[r,j] = sum_{h,m} xl[r,h]*x0[r,m]*W[h*32+m,j]; r = b*16+d.
// R8: 256 threads / 8 warps (2M x 4N, warp tile 32x32, acc 32 regs),
//     __launch_bounds__(256,2) -> 16 warps/SM on dual-CTA SMs.
//     No split-K; barrier-free epilogue.

namespace {
constexpr int RTOT = 16384;           // 1024 batches * 16 emb rows
constexpr int NOUT = 128;
constexpr int OUTW = 384;
constexpr int TM   = 64;              // rows per CTA (= 4 batches)
constexpr int NCTA = RTOT / TM;       // 256
constexpr int NTHR = 256;
constexpr int KC   = 128;             // K per chunk

// SMEM layout (bytes)
constexpr int OFF_A    = 0;                        // 2 stages x 16384 (64r x 128k)
constexpr int OFF_B    = 32768;                    // 2 stages x 32768 (128n x 128k)
constexpr int OFF_X0   = 98304;                    // float[64][33]
constexpr int OFF_BIAS = OFF_X0 + 64 * 33 * 4;     // 106752
constexpr int SMEM_TOTAL = OFF_BIAS + 512;         // 107264
}

// device-global scratch (allocation-free rule)
__device__ __align__(16) __half g_Wt[128 * (1024 + 4096 + 4096)]; // [layer][j][k]
__device__ __align__(16) float  g_xlA[RTOT * NOUT];  // transposed [col][row]
__device__ __align__(16) float  g_xlB[RTOT * NOUT];

// ---------------- helpers ----------------
__device__ __forceinline__ uint32_t smem_u32(const void* p) {
    uint32_t a;
    asm("{ .reg .u64 t; cvta.to.shared.u64 t, %1; cvt.u32.u64 %0, t; }" : "=r"(a) : "l"(p));
    return a;
}
__device__ __forceinline__ void ldsm4(uint32_t* r, uint32_t addr) {
    asm volatile("ldmatrix.sync.aligned.m8n8.x4.shared.b16 {%0,%1,%2,%3}, [%4];"
                 : "=r"(r[0]), "=r"(r[1]), "=r"(r[2]), "=r"(r[3]) : "r"(addr));
}
__device__ __forceinline__ void mma16816(float* c, const uint32_t* a, const uint32_t* b) {
    asm volatile("mma.sync.aligned.m16n8k16.row.col.f32.f16.f16.f32 "
                 "{%0,%1,%2,%3}, {%4,%5,%6,%7}, {%8,%9}, {%0,%1,%2,%3};"
                 : "+f"(c[0]), "+f"(c[1]), "+f"(c[2]), "+f"(c[3])
                 : "r"(a[0]), "r"(a[1]), "r"(a[2]), "r"(a[3]), "r"(b[0]), "r"(b[1]));
}
#define CP_ASYNC16(dst, src) \
    asm volatile("cp.async.cg.shared.global [%0], [%1], 16;" :: "r"(dst), "l"(src) : "memory")
#define CP_COMMIT()  asm volatile("cp.async.commit_group;" ::: "memory")
#define CP_WAIT0()   asm volatile("cp.async.wait_group 0;" ::: "memory")

// ---------------- W transpose + fp16 convert ----------------
template <int LAYER>
__global__ void wprep(const float* __restrict__ W) {
    constexpr int K    = (LAYER == 0) ? 1024 : 4096;
    constexpr int WOFF = (LAYER == 0) ? 0 : (LAYER == 1 ? 131072 : 655360);
    __half* Wt = g_Wt + WOFF;
    __shared__ float s[32][129];
    const int k0 = blockIdx.x * 32;
    const int t  = threadIdx.x;
#pragma unroll
    for (int i = 0; i < 16; i++) {
        int idx = t + i * 256;
        int kk = idx >> 7, j = idx & 127;
        s[kk][j] = W[(size_t)(k0 + kk) * 128 + j];
    }
    __syncthreads();
    const int j = t >> 1, hb = t & 1;
#pragma unroll
    for (int r = 0; r < 2; r++) {
        uint32_t w[4];
#pragma unroll
        for (int e = 0; e < 4; e++) {
            int kk = hb * 16 + r * 8 + e * 2;
            __half2 h2 = __floats2half2_rn(s[kk][j], s[kk + 1][j]);
            w[e] = *reinterpret_cast<uint32_t*>(&h2);
        }
        *reinterpret_cast<uint4*>(Wt + (size_t)j * K + k0 + hb * 16 + r * 8) =
            make_uint4(w[0], w[1], w[2], w[3]);
    }
}

// ---------------- main layer kernel ----------------
template <int LAYER>
__global__ __launch_bounds__(NTHR, 2)
void cin_mma(const float* __restrict__ inputs,
             const float* __restrict__ bias,
             float* __restrict__ out)
{
    constexpr int  K    = (LAYER == 0) ? 1024 : 4096;
    constexpr int  WOFF = (LAYER == 0) ? 0 : (LAYER == 1 ? 131072 : 655360);
    constexpr int  NC   = K / KC;          // 8 / 32 chunks
    constexpr bool RELU = (LAYER < 2);
    constexpr bool WXL  = (LAYER < 2);

    extern __shared__ char smem[];
    const uint32_t sb = smem_u32(smem);

    const int tid  = threadIdx.x;
    const int wid  = tid >> 5;
    const int lane = tid & 31;
    const int blk  = blockIdx.x;
    const int R0   = blk * TM;

    const __half* Wt     = g_Wt + WOFF;
    const float*  xl_in  = (LAYER == 2) ? g_xlB : g_xlA;
    float*        xl_out = (LAYER == 0) ? g_xlA : g_xlB;

    // ---- B chunk prefetch: [n=128][k=128], 2 atom-cols of 16KB ----
    auto issue_b = [&](int cc) {
        const int s = cc & 1;
        const __half* wsrc = Wt + cc * KC;
        const uint32_t bbase = sb + OFF_B + s * 32768;
#pragma unroll
        for (int i = 0; i < 8; i++) {
            int idx = tid + i * NTHR;
            int j = idx >> 4, q = idx & 15;          // n-row, 16B unit
            const __half* g = wsrc + (size_t)j * K + q * 8;
            uint32_t d = bbase + (q >> 3) * 16384 + j * 128
                       + ((uint32_t)((q & 7) * 16) ^ ((j & 7) << 4));
            CP_ASYNC16(d, g);
        }
        CP_COMMIT();
    };

    issue_b(0);

    // ---- x0 tile (4 batches, contiguous 2048 floats) + bias -> SMEM ----
    {
        const float* src = inputs + (size_t)blk * 2048;
        float* x0sw = reinterpret_cast<float*>(smem + OFF_X0);
#pragma unroll
        for (int i = 0; i < 8; i++) {
            int idx = tid + i * NTHR;
            int bb = idx >> 9, m = (idx >> 4) & 31, d = idx & 15;
            x0sw[(bb * 16 + d) * 33 + m] = src[idx];
        }
        if (tid < 128) reinterpret_cast<float*>(smem + OFF_BIAS)[tid] = bias[tid];
    }
    __syncthreads();

    // ---- Z-gen setup: 4 threads per row; each thread owns one h per chunk ----
    const int row = tid >> 2;      // 0..63
    const int sub = tid & 3;       // h index within chunk (KC=128 -> 4 h values)
    const float* x0s = reinterpret_cast<const float*>(smem + OFF_X0);
    __half2 x0h[16];               // full x0 row as half2
#pragma unroll
    for (int i = 0; i < 16; i++)
        x0h[i] = __floats2half2_rn(x0s[row * 33 + 2 * i], x0s[row * 33 + 2 * i + 1]);
    const uint32_t xorv = (uint32_t)(row & 7) << 4;
    // A stage layout: atom(k>>6)*8192 + row*128 + (((k&63)*2) ^ ((row&7)<<4))
    // this thread's k range: sub*32 .. sub*32+31  (atom = sub>>1)
    char* const agen = smem + OFF_A + (sub >> 1) * 8192 + row * 128;

    auto gen_z = [&](int cc) {
        const int h = cc * 4 + sub;
        __half xlh;
        if (LAYER == 0) {
            __half2 hp = x0h[h >> 1];
            xlh = (h & 1) ? __high2half(hp) : __low2half(hp);
        } else {
            xlh = __float2half_rn(__ldg(&xl_in[(size_t)h * RTOT + R0 + row]));
        }
        const __half2 xl2 = __half2half2(xlh);
        char* base = agen + (cc & 1) * 16384;
#pragma unroll
        for (int q = 0; q < 4; q++) {
            uint32_t w[4];
#pragma unroll
            for (int e = 0; e < 4; e++) {
                __half2 h2 = __hmul2(x0h[q * 4 + e], xl2);
                w[e] = *reinterpret_cast<uint32_t*>(&h2);
            }
            const uint32_t off = (uint32_t)((sub & 1) * 64 + q * 16) ^ xorv;
            *reinterpret_cast<uint4*>(base + off) = make_uint4(w[0], w[1], w[2], w[3]);
        }
    };

    gen_z(0);   // prologue: A[0]

    // ---- accumulators: warp tile 32(M) x 32(N); warps = 2M x 4N ----
    float acc[2][4][4];
#pragma unroll
    for (int mt = 0; mt < 2; mt++)
#pragma unroll
        for (int nt = 0; nt < 4; nt++)
#pragma unroll
            for (int e = 0; e < 4; e++) acc[mt][nt][e] = 0.f;

    const int mg = wid >> 2;        // M group (0/1): rows mg*32..mg*32+31
    const int ng = wid & 3;         // N group: cols ng*32..ng*32+31
    const int g  = lane >> 3;       // ldmatrix address group

    // ================= main K loop (one barrier per 128-K chunk) =============
    for (int c = 0; c < NC; c++) {
        const int sA = c & 1;

        CP_WAIT0();                // B(c) landed (only group outstanding)
        __syncthreads();           // A[sA] gen'd + B[sA] visible to all

        if (c + 1 < NC) {
            issue_b(c + 1);        // stage sA^1: last read in chunk c-1, safe
            gen_z(c + 1);
        }

        // ---- compute chunk c: 8 k16 steps x (2 A-ldsm + 2 B-ldsm + 8 mma) ----
        const uint32_t abase = sb + OFF_A + sA * 16384;
        const uint32_t bbase = sb + OFF_B + sA * 32768;
#pragma unroll
        for (int ks = 0; ks < 8; ks++) {
            const int k0 = ks * 16;
            uint32_t afr[2][4];
#pragma unroll
            for (int mt = 0; mt < 2; mt++) {
                const int ar = mg * 32 + mt * 16 + (g & 1) * 8 + (lane & 7);
                const int ak = k0 + (g >> 1) * 8;
                ldsm4(afr[mt], abase + (ak >> 6) * 8192 + ar * 128
                               + (((uint32_t)(ak & 63) * 2) ^ ((ar & 7) << 4)));
            }
            uint32_t bfr[4][2];
#pragma unroll
            for (int bt = 0; bt < 2; bt++) {
                const int br = ng * 32 + bt * 16 + (g >> 1) * 8 + (lane & 7);
                const int bk = k0 + (g & 1) * 8;
                uint32_t r[4];
                ldsm4(r, bbase + (bk >> 6) * 16384 + br * 128
                         + (((uint32_t)(bk & 63) * 2) ^ ((br & 7) << 4)));
                bfr[bt * 2][0] = r[0]; bfr[bt * 2][1] = r[1];
                bfr[bt * 2 + 1][0] = r[2]; bfr[bt * 2 + 1][1] = r[3];
            }
#pragma unroll
            for (int mt = 0; mt < 2; mt++)
#pragma unroll
                for (int nt = 0; nt < 4; nt++)
                    mma16816(acc[mt][nt], afr[mt], bfr[nt]);
        }
    }

    // ================= epilogue (no reduction: disjoint 32x32 tiles) ========
    const float* biass = reinterpret_cast<const float*>(smem + OFF_BIAS);
#pragma unroll
    for (int mt = 0; mt < 2; mt++) {
        const int batch = blk * 4 + mg * 2 + mt;     // one m16 tile == one batch
        const int r0 = R0 + mg * 32 + mt * 16 + (lane >> 2);
#pragma unroll
        for (int nt = 0; nt < 4; nt++) {
            const int j0 = ng * 32 + nt * 8 + (lane & 3) * 2;
            const float b0 = biass[j0], b1 = biass[j0 + 1];
            float v0 = acc[mt][nt][0] + b0;
            float v1 = acc[mt][nt][1] + b1;
            float v2 = acc[mt][nt][2] + b0;
            float v3 = acc[mt][nt][3] + b1;
            if (RELU) {
                v0 = fmaxf(v0, 0.f); v1 = fmaxf(v1, 0.f);
                v2 = fmaxf(v2, 0.f); v3 = fmaxf(v3, 0.f);
            }
            if (WXL) {
                xl_out[(size_t)j0 * RTOT + r0]           = v0;
                xl_out[(size_t)(j0 + 1) * RTOT + r0]     = v1;
                xl_out[(size_t)j0 * RTOT + r0 + 8]       = v2;
                xl_out[(size_t)(j0 + 1) * RTOT + r0 + 8] = v3;
            }
            float s0 = v0 + v2, s1 = v1 + v3;        // rows r, r+8
            s0 += __shfl_xor_sync(0xffffffffu, s0, 4);
            s1 += __shfl_xor_sync(0xffffffffu, s1, 4);
            s0 += __shfl_xor_sync(0xffffffffu, s0, 8);
            s1 += __shfl_xor_sync(0xffffffffu, s1, 8);
            s0 += __shfl_xor_sync(0xffffffffu, s0, 16);
            s1 += __shfl_xor_sync(0xffffffffu, s1, 16);
            if (lane < 4) {
                float* dst = out + (size_t)batch * OUTW + LAYER * NOUT
                           + ng * 32 + nt * 8 + lane * 2;
                dst[0] = s0;
                dst[1] = s1;
            }
        }
    }
}

// ---------------- host ----------------
extern "C" void kernel_launch(void* const* d_in, const int* in_sizes, int n_in,
                              void* d_out, int out_size)
{
    const float* inputs = (const float*)d_in[0];
    const float* W0     = (const float*)d_in[1];
    const float* b0     = (const float*)d_in[2];
    const float* W1     = (const float*)d_in[3];
    const float* b1     = (const float*)d_in[4];
    const float* W2     = (const float*)d_in[5];
    const float* b2     = (const float*)d_in[6];
    float* out = (float*)d_out;

    cudaFuncSetAttribute(cin_mma<0>, cudaFuncAttributeMaxDynamicSharedMemorySize, SMEM_TOTAL);
    cudaFuncSetAttribute(cin_mma<1>, cudaFuncAttributeMaxDynamicSharedMemorySize, SMEM_TOTAL);
    cudaFuncSetAttribute(cin_mma<2>, cudaFuncAttributeMaxDynamicSharedMemorySize, SMEM_TOTAL);

    wprep<0><<<32,  256>>>(W0);
    wprep<1><<<128, 256>>>(W1);
    wprep<2><<<128, 256>>>(W2);

    cin_mma<0><<<NCTA, NTHR, SMEM_TOTAL>>>(inputs, b0, out);
    cin_mma<1><<<NCTA, NTHR, SMEM_TOTAL>>>(inputs, b1, out);
    cin_mma<2><<<NCTA, NTHR, SMEM_TOTAL>>>(inputs, b2, out);
}

// round 9
// speedup vs baseline: 1.0102x; 1.0102x over previous
#include <cuda_runtime.h>
#include <cuda_fp16.h>
#include <cstdint>

// CIN via mma.sync (base-ISA tensor cores).
// out[r,j] = sum_{h,m} xl[r,h]*x0[r,m]*W[h*32+m,j]; r = b*16+d.
// R9: B tiles stored pre-swizzled chunk-major in global; ONE cp.async.bulk
//     (32KB) + mbarrier per chunk instead of 2048 cp.async ops (the measured
//     LSU-issue wall of R4-R8).

namespace {
constexpr int RTOT = 16384;           // 1024 batches * 16 emb rows
constexpr int NOUT = 128;
constexpr int OUTW = 384;
constexpr int TM   = 64;              // rows per CTA (= 4 batches)
constexpr int NCTA = RTOT / TM;       // 256
constexpr int NTHR = 256;
constexpr int KC   = 128;             // K per chunk
constexpr int CHUNK_BYTES = 128 * KC * 2;   // 32768

// SMEM layout (bytes)
constexpr int OFF_A    = 0;                        // 2 stages x 16384 (64r x 128k)
constexpr int OFF_B    = 32768;                    // 2 stages x 32768 (128n x 128k)
constexpr int OFF_X0   = 98304;                    // float[64][33]
constexpr int OFF_BIAS = OFF_X0 + 64 * 33 * 4;     // 106752
constexpr int OFF_MBAR = OFF_BIAS + 512;           // 107264: 2 x 8B mbarriers
constexpr int SMEM_TOTAL = OFF_MBAR + 16;          // 107280
}

// device-global scratch (allocation-free rule)
// g_Wt: per layer, chunk-major pre-swizzled byte image:
//   byte off = c*32768 + (kk>>6)*16384 + j*128 + (((kk&63)*2) ^ ((j&7)<<4))
//   (j = output col 0..127, kk = k within chunk 0..127)
__device__ __align__(128) __half g_Wt[128 * (1024 + 4096 + 4096)];
__device__ __align__(16) float  g_xlA[RTOT * NOUT];  // transposed [col][row]
__device__ __align__(16) float  g_xlB[RTOT * NOUT];

// ---------------- helpers ----------------
__device__ __forceinline__ uint32_t smem_u32(const void* p) {
    uint32_t a;
    asm("{ .reg .u64 t; cvta.to.shared.u64 t, %1; cvt.u32.u64 %0, t; }" : "=r"(a) : "l"(p));
    return a;
}
__device__ __forceinline__ void ldsm4(uint32_t* r, uint32_t addr) {
    asm volatile("ldmatrix.sync.aligned.m8n8.x4.shared.b16 {%0,%1,%2,%3}, [%4];"
                 : "=r"(r[0]), "=r"(r[1]), "=r"(r[2]), "=r"(r[3]) : "r"(addr));
}
__device__ __forceinline__ void mma16816(float* c, const uint32_t* a, const uint32_t* b) {
    asm volatile("mma.sync.aligned.m16n8k16.row.col.f32.f16.f16.f32 "
                 "{%0,%1,%2,%3}, {%4,%5,%6,%7}, {%8,%9}, {%0,%1,%2,%3};"
                 : "+f"(c[0]), "+f"(c[1]), "+f"(c[2]), "+f"(c[3])
                 : "r"(a[0]), "r"(a[1]), "r"(a[2]), "r"(a[3]), "r"(b[0]), "r"(b[1]));
}
#define MBAR_INIT(mb, n) \
    asm volatile("mbarrier.init.shared.b64 [%0], %1;" :: "r"((uint32_t)(mb)), "r"((uint32_t)(n)) : "memory")
#define MBAR_EXPECT_TX(mb, tx) \
    asm volatile("mbarrier.arrive.expect_tx.shared.b64 _, [%0], %1;" :: "r"((uint32_t)(mb)), "r"((uint32_t)(tx)) : "memory")
#define MBAR_WAIT(mb, ph) \
    asm volatile("{\n\t.reg .pred p;\n\t" \
        "WL_%=:\n\t" \
        "mbarrier.try_wait.parity.shared.b64 p, [%0], %1;\n\t" \
        "@!p bra WL_%=;\n\t}" :: "r"((uint32_t)(mb)), "r"((uint32_t)(ph)) : "memory")
#define BULK_CP(dst, src, bytes, mb) \
    asm volatile("cp.async.bulk.shared::cta.global.mbarrier::complete_tx::bytes [%0], [%1], %2, [%3];" \
                 :: "r"((uint32_t)(dst)), "l"(src), "r"((uint32_t)(bytes)), "r"((uint32_t)(mb)) : "memory")

// ---------------- W -> chunk-major pre-swizzled fp16 image ----------------
template <int LAYER>
__global__ void wprep(const float* __restrict__ W) {
    constexpr int K    = (LAYER == 0) ? 1024 : 4096;
    constexpr int WOFF = (LAYER == 0) ? 0 : (LAYER == 1 ? 131072 : 655360);
    char* Wt = reinterpret_cast<char*>(g_Wt + WOFF);
    __shared__ float s[32][129];
    const int k0 = blockIdx.x * 32;               // 32 consecutive k rows
    const int t  = threadIdx.x;
#pragma unroll
    for (int i = 0; i < 16; i++) {
        int idx = t + i * 256;
        int kk = idx >> 7, j = idx & 127;
        s[kk][j] = W[(size_t)(k0 + kk) * 128 + j];
    }
    __syncthreads();
    const int j = t >> 1, hb = t & 1;
    const int c = k0 >> 7;                        // chunk id (32 rows within one chunk)
#pragma unroll
    for (int r = 0; r < 2; r++) {
        uint32_t w[4];
        const int kk = (k0 & 127) + hb * 16 + r * 8;   // k within chunk, 8-aligned
#pragma unroll
        for (int e = 0; e < 4; e++) {
            int kl = hb * 16 + r * 8 + e * 2;          // k within this 32-block
            __half2 h2 = __floats2half2_rn(s[kl][j], s[kl + 1][j]);
            w[e] = *reinterpret_cast<uint32_t*>(&h2);
        }
        size_t off = (size_t)c * 32768 + (kk >> 6) * 16384 + j * 128
                   + (((uint32_t)(kk & 63) * 2) ^ ((uint32_t)(j & 7) << 4));
        *reinterpret_cast<uint4*>(Wt + off) = make_uint4(w[0], w[1], w[2], w[3]);
    }
}

// ---------------- main layer kernel ----------------
template <int LAYER>
__global__ __launch_bounds__(NTHR, 2)
void cin_mma(const float* __restrict__ inputs,
             const float* __restrict__ bias,
             float* __restrict__ out)
{
    constexpr int  K    = (LAYER == 0) ? 1024 : 4096;
    constexpr int  WOFF = (LAYER == 0) ? 0 : (LAYER == 1 ? 131072 : 655360);
    constexpr int  NC   = K / KC;          // 8 / 32 chunks
    constexpr bool RELU = (LAYER < 2);
    constexpr bool WXL  = (LAYER < 2);

    extern __shared__ char smem[];
    const uint32_t sb = smem_u32(smem);

    const int tid  = threadIdx.x;
    const int wid  = tid >> 5;
    const int lane = tid & 31;
    const int blk  = blockIdx.x;
    const int R0   = blk * TM;

    const char*  Wt     = reinterpret_cast<const char*>(g_Wt + WOFF);
    const float* xl_in  = (LAYER == 2) ? g_xlB : g_xlA;
    float*       xl_out = (LAYER == 0) ? g_xlA : g_xlB;

    // ---- mbarrier init + first B bulk copy ----
    if (tid == 0) {
        MBAR_INIT(sb + OFF_MBAR + 0, 1);
        MBAR_INIT(sb + OFF_MBAR + 8, 1);
    }
    __syncthreads();            // mbarriers visible
    if (tid == 0) {
        MBAR_EXPECT_TX(sb + OFF_MBAR + 0, CHUNK_BYTES);
        BULK_CP(sb + OFF_B, Wt, CHUNK_BYTES, sb + OFF_MBAR + 0);
    }

    // ---- x0 tile (4 batches, contiguous 2048 floats) + bias -> SMEM ----
    {
        const float* src = inputs + (size_t)blk * 2048;
        float* x0sw = reinterpret_cast<float*>(smem + OFF_X0);
#pragma unroll
        for (int i = 0; i < 8; i++) {
            int idx = tid + i * NTHR;
            int bb = idx >> 9, m = (idx >> 4) & 31, d = idx & 15;
            x0sw[(bb * 16 + d) * 33 + m] = src[idx];
        }
        if (tid < 128) reinterpret_cast<float*>(smem + OFF_BIAS)[tid] = bias[tid];
    }
    __syncthreads();

    // ---- Z-gen setup: 4 threads per row; each thread owns one h per chunk ----
    const int row = tid >> 2;      // 0..63
    const int sub = tid & 3;       // h index within chunk
    const float* x0s = reinterpret_cast<const float*>(smem + OFF_X0);
    __half2 x0h[16];
#pragma unroll
    for (int i = 0; i < 16; i++)
        x0h[i] = __floats2half2_rn(x0s[row * 33 + 2 * i], x0s[row * 33 + 2 * i + 1]);
    const uint32_t xorv = (uint32_t)(row & 7) << 4;
    // A stage layout: atom(k>>6)*8192 + row*128 + (((k&63)*2) ^ ((row&7)<<4))
    char* const agen = smem + OFF_A + (sub >> 1) * 8192 + row * 128;

    auto gen_z = [&](int cc) {
        const int h = cc * 4 + sub;
        __half xlh;
        if (LAYER == 0) {
            __half2 hp = x0h[h >> 1];
            xlh = (h & 1) ? __high2half(hp) : __low2half(hp);
        } else {
            xlh = __float2half_rn(__ldg(&xl_in[(size_t)h * RTOT + R0 + row]));
        }
        const __half2 xl2 = __half2half2(xlh);
        char* base = agen + (cc & 1) * 16384;
#pragma unroll
        for (int q = 0; q < 4; q++) {
            uint32_t w[4];
#pragma unroll
            for (int e = 0; e < 4; e++) {
                __half2 h2 = __hmul2(x0h[q * 4 + e], xl2);
                w[e] = *reinterpret_cast<uint32_t*>(&h2);
            }
            const uint32_t off = (uint32_t)((sub & 1) * 64 + q * 16) ^ xorv;
            *reinterpret_cast<uint4*>(base + off) = make_uint4(w[0], w[1], w[2], w[3]);
        }
    };

    gen_z(0);   // prologue: A[0]

    // ---- accumulators: warp tile 32(M) x 32(N); warps = 2M x 4N ----
    float acc[2][4][4];
#pragma unroll
    for (int mt = 0; mt < 2; mt++)
#pragma unroll
        for (int nt = 0; nt < 4; nt++)
#pragma unroll
            for (int e = 0; e < 4; e++) acc[mt][nt][e] = 0.f;

    const int mg = wid >> 2;        // M group (0/1)
    const int ng = wid & 3;         // N group
    const int g  = lane >> 3;       // ldmatrix address group

    // ================= main K loop =================
    for (int c = 0; c < NC; c++) {
        const int sA = c & 1;

        MBAR_WAIT(sb + OFF_MBAR + 8 * sA, (c >> 1) & 1);  // B(c) landed
        __syncthreads();   // A[sA] gen'd by all; stage sA^1 fully consumed (c-1)

        if (c + 1 < NC) {
            if (tid == 0) {
                MBAR_EXPECT_TX(sb + OFF_MBAR + 8 * (sA ^ 1), CHUNK_BYTES);
                BULK_CP(sb + OFF_B + (sA ^ 1) * 32768,
                        Wt + (size_t)(c + 1) * CHUNK_BYTES,
                        CHUNK_BYTES, sb + OFF_MBAR + 8 * (sA ^ 1));
            }
            gen_z(c + 1);
        }

        // ---- compute chunk c: 8 k16 steps x (2 A-ldsm + 2 B-ldsm + 8 mma) ----
        const uint32_t abase = sb + OFF_A + sA * 16384;
        const uint32_t bbase = sb + OFF_B + sA * 32768;
#pragma unroll
        for (int ks = 0; ks < 8; ks++) {
            const int k0 = ks * 16;
            uint32_t afr[2][4];
#pragma unroll
            for (int mt = 0; mt < 2; mt++) {
                const int ar = mg * 32 + mt * 16 + (g & 1) * 8 + (lane & 7);
                const int ak = k0 + (g >> 1) * 8;
                ldsm4(afr[mt], abase + (ak >> 6) * 8192 + ar * 128
                               + (((uint32_t)(ak & 63) * 2) ^ ((ar & 7) << 4)));
            }
            uint32_t bfr[4][2];
#pragma unroll
            for (int bt = 0; bt < 2; bt++) {
                const int br = ng * 32 + bt * 16 + (g >> 1) * 8 + (lane & 7);
                const int bk = k0 + (g & 1) * 8;
                uint32_t r[4];
                ldsm4(r, bbase + (bk >> 6) * 16384 + br * 128
                         + (((uint32_t)(bk & 63) * 2) ^ ((br & 7) << 4)));
                bfr[bt * 2][0] = r[0]; bfr[bt * 2][1] = r[1];
                bfr[bt * 2 + 1][0] = r[2]; bfr[bt * 2 + 1][1] = r[3];
            }
#pragma unroll
            for (int mt = 0; mt < 2; mt++)
#pragma unroll
                for (int nt = 0; nt < 4; nt++)
                    mma16816(acc[mt][nt], afr[mt], bfr[nt]);
        }
    }

    // ================= epilogue (disjoint 32x32 tiles) ======================
    const float* biass = reinterpret_cast<const float*>(smem + OFF_BIAS);
#pragma unroll
    for (int mt = 0; mt < 2; mt++) {
        const int batch = blk * 4 + mg * 2 + mt;     // one m16 tile == one batch
        const int r0 = R0 + mg * 32 + mt * 16 + (lane >> 2);
#pragma unroll
        for (int nt = 0; nt < 4; nt++) {
            const int j0 = ng * 32 + nt * 8 + (lane & 3) * 2;
            const float b0 = biass[j0], b1 = biass[j0 + 1];
            float v0 = acc[mt][nt][0] + b0;
            float v1 = acc[mt][nt][1] + b1;
            float v2 = acc[mt][nt][2] + b0;
            float v3 = acc[mt][nt][3] + b1;
            if (RELU) {
                v0 = fmaxf(v0, 0.f); v1 = fmaxf(v1, 0.f);
                v2 = fmaxf(v2, 0.f); v3 = fmaxf(v3, 0.f);
            }
            if (WXL) {
                xl_out[(size_t)j0 * RTOT + r0]           = v0;
                xl_out[(size_t)(j0 + 1) * RTOT + r0]     = v1;
                xl_out[(size_t)j0 * RTOT + r0 + 8]       = v2;
                xl_out[(size_t)(j0 + 1) * RTOT + r0 + 8] = v3;
            }
            float s0 = v0 + v2, s1 = v1 + v3;        // rows r, r+8
            s0 += __shfl_xor_sync(0xffffffffu, s0, 4);
            s1 += __shfl_xor_sync(0xffffffffu, s1, 4);
            s0 += __shfl_xor_sync(0xffffffffu, s0, 8);
            s1 += __shfl_xor_sync(0xffffffffu, s1, 8);
            s0 += __shfl_xor_sync(0xffffffffu, s0, 16);
            s1 += __shfl_xor_sync(0xffffffffu, s1, 16);
            if (lane < 4) {
                float* dst = out + (size_t)batch * OUTW + LAYER * NOUT
                           + ng * 32 + nt * 8 + lane * 2;
                dst[0] = s0;
                dst[1] = s1;
            }
        }
    }
}

// ---------------- host ----------------
extern "C" void kernel_launch(void* const* d_in, const int* in_sizes, int n_in,
                              void* d_out, int out_size)
{
    const float* inputs = (const float*)d_in[0];
    const float* W0     = (const float*)d_in[1];
    const float* b0     = (const float*)d_in[2];
    const float* W1     = (const float*)d_in[3];
    const float* b1     = (const float*)d_in[4];
    const float* W2     = (const float*)d_in[5];
    const float* b2     = (const float*)d_in[6];
    float* out = (float*)d_out;

    cudaFuncSetAttribute(cin_mma<0>, cudaFuncAttributeMaxDynamicSharedMemorySize, SMEM_TOTAL);
    cudaFuncSetAttribute(cin_mma<1>, cudaFuncAttributeMaxDynamicSharedMemorySize, SMEM_TOTAL);
    cudaFuncSetAttribute(cin_mma<2>, cudaFuncAttributeMaxDynamicSharedMemorySize, SMEM_TOTAL);

    wprep<0><<<32,  256>>>(W0);
    wprep<1><<<128, 256>>>(W1);
    wprep<2><<<128, 256>>>(W2);

    cin_mma<0><<<NCTA, NTHR, SMEM_TOTAL>>>(inputs, b0, out);
    cin_mma<1><<<NCTA, NTHR, SMEM_TOTAL>>>(inputs, b1, out);
    cin_mma<2><<<NCTA, NTHR, SMEM_TOTAL>>>(inputs, b2, out);
}

// round 10
// speedup vs baseline: 1.2628x; 1.2501x over previous
#include <cuda_runtime.h>
#include <cuda_fp16.h>
#include <cstdint>

// CIN via mma.sync (base-ISA tensor cores).
// out[r,j] = sum_{h,m} xl[r,h]*x0[r,m]*W[h*32+m,j]; r = b*16+d.
// R10: A (=Z) built directly in mma fragment registers (16 half2 of x0 per
//      thread + 4 HMUL2 per tile) — no A SMEM, no A ldsm, no gen/sync chain.
//      B: pre-swizzled chunk-major image + cp.async.bulk (R9 path).

namespace {
constexpr int RTOT = 16384;           // 1024 batches * 16 emb rows
constexpr int NOUT = 128;
constexpr int OUTW = 384;
constexpr int TM   = 64;              // rows per CTA (= 4 batches)
constexpr int NCTA = RTOT / TM;       // 256
constexpr int NTHR = 256;
constexpr int KC   = 128;             // K per chunk
constexpr int CHUNK_BYTES = 128 * KC * 2;   // 32768

// SMEM layout (bytes)
constexpr int OFF_B    = 0;                        // 2 stages x 32768
constexpr int OFF_X0   = 65536;                    // float[64][33] = 8448
constexpr int OFF_BIAS = 73984;                    // 512
constexpr int OFF_XL   = 74496;                    // 2 stages x 1024 (float[4][64])
constexpr int OFF_MBAR = 76544;                    // 2 x 8B
constexpr int SMEM_TOTAL = 76560;
}

// device-global scratch (allocation-free rule)
// g_Wt: per layer, chunk-major pre-swizzled byte image:
//   byte off = c*32768 + (kk>>6)*16384 + j*128 + (((kk&63)*2) ^ ((j&7)<<4))
__device__ __align__(128) __half g_Wt[128 * (1024 + 4096 + 4096)];
__device__ __align__(16) float  g_xlA[RTOT * NOUT];  // transposed [col][row]
__device__ __align__(16) float  g_xlB[RTOT * NOUT];

// ---------------- helpers ----------------
__device__ __forceinline__ uint32_t smem_u32(const void* p) {
    uint32_t a;
    asm("{ .reg .u64 t; cvta.to.shared.u64 t, %1; cvt.u32.u64 %0, t; }" : "=r"(a) : "l"(p));
    return a;
}
__device__ __forceinline__ void ldsm4(uint32_t* r, uint32_t addr) {
    asm volatile("ldmatrix.sync.aligned.m8n8.x4.shared.b16 {%0,%1,%2,%3}, [%4];"
                 : "=r"(r[0]), "=r"(r[1]), "=r"(r[2]), "=r"(r[3]) : "r"(addr));
}
__device__ __forceinline__ void mma16816(float* c, const uint32_t* a, const uint32_t* b) {
    asm volatile("mma.sync.aligned.m16n8k16.row.col.f32.f16.f16.f32 "
                 "{%0,%1,%2,%3}, {%4,%5,%6,%7}, {%8,%9}, {%0,%1,%2,%3};"
                 : "+f"(c[0]), "+f"(c[1]), "+f"(c[2]), "+f"(c[3])
                 : "r"(a[0]), "r"(a[1]), "r"(a[2]), "r"(a[3]), "r"(b[0]), "r"(b[1]));
}
__device__ __forceinline__ uint32_t h2u(__half2 h) {
    return *reinterpret_cast<uint32_t*>(&h);
}
#define MBAR_INIT(mb, n) \
    asm volatile("mbarrier.init.shared.b64 [%0], %1;" :: "r"((uint32_t)(mb)), "r"((uint32_t)(n)) : "memory")
#define MBAR_EXPECT_TX(mb, tx) \
    asm volatile("mbarrier.arrive.expect_tx.shared.b64 _, [%0], %1;" :: "r"((uint32_t)(mb)), "r"((uint32_t)(tx)) : "memory")
#define MBAR_WAIT(mb, ph) \
    asm volatile("{\n\t.reg .pred p;\n\t" \
        "WL_%=:\n\t" \
        "mbarrier.try_wait.parity.shared.b64 p, [%0], %1;\n\t" \
        "@!p bra WL_%=;\n\t}" :: "r"((uint32_t)(mb)), "r"((uint32_t)(ph)) : "memory")
#define BULK_CP(dst, src, bytes, mb) \
    asm volatile("cp.async.bulk.shared::cta.global.mbarrier::complete_tx::bytes [%0], [%1], %2, [%3];" \
                 :: "r"((uint32_t)(dst)), "l"(src), "r"((uint32_t)(bytes)), "r"((uint32_t)(mb)) : "memory")

// ---------------- W -> chunk-major pre-swizzled fp16 image ----------------
template <int LAYER>
__global__ void wprep(const float* __restrict__ W) {
    constexpr int WOFF = (LAYER == 0) ? 0 : (LAYER == 1 ? 131072 : 655360);
    char* Wt = reinterpret_cast<char*>(g_Wt + WOFF);
    __shared__ float s[32][129];
    const int k0 = blockIdx.x * 32;               // 32 consecutive k rows
    const int t  = threadIdx.x;
#pragma unroll
    for (int i = 0; i < 16; i++) {
        int idx = t + i * 256;
        int kk = idx >> 7, j = idx & 127;
        s[kk][j] = W[(size_t)(k0 + kk) * 128 + j];
    }
    __syncthreads();
    const int j = t >> 1, hb = t & 1;
    const int c = k0 >> 7;                        // chunk id
#pragma unroll
    for (int r = 0; r < 2; r++) {
        uint32_t w[4];
        const int kk = (k0 & 127) + hb * 16 + r * 8;   // k within chunk
#pragma unroll
        for (int e = 0; e < 4; e++) {
            int kl = hb * 16 + r * 8 + e * 2;
            __half2 h2 = __floats2half2_rn(s[kl][j], s[kl + 1][j]);
            w[e] = *reinterpret_cast<uint32_t*>(&h2);
        }
        size_t off = (size_t)c * 32768 + (kk >> 6) * 16384 + j * 128
                   + (((uint32_t)(kk & 63) * 2) ^ ((uint32_t)(j & 7) << 4));
        *reinterpret_cast<uint4*>(Wt + off) = make_uint4(w[0], w[1], w[2], w[3]);
    }
}

// ---------------- main layer kernel ----------------
template <int LAYER>
__global__ __launch_bounds__(NTHR, 2)
void cin_mma(const float* __restrict__ inputs,
             const float* __restrict__ bias,
             float* __restrict__ out)
{
    constexpr int  K    = (LAYER == 0) ? 1024 : 4096;
    constexpr int  WOFF = (LAYER == 0) ? 0 : (LAYER == 1 ? 131072 : 655360);
    constexpr int  NC   = K / KC;          // 8 / 32 chunks
    constexpr bool RELU = (LAYER < 2);
    constexpr bool WXL  = (LAYER < 2);

    extern __shared__ char smem[];
    const uint32_t sb = smem_u32(smem);

    const int tid  = threadIdx.x;
    const int wid  = tid >> 5;
    const int lane = tid & 31;
    const int blk  = blockIdx.x;
    const int R0   = blk * TM;

    const char*  Wt     = reinterpret_cast<const char*>(g_Wt + WOFF);
    const float* xl_in  = (LAYER == 2) ? g_xlB : g_xlA;
    float*       xl_out = (LAYER == 0) ? g_xlA : g_xlB;

    // ---- mbarrier init + first B bulk copy ----
    if (tid == 0) {
        MBAR_INIT(sb + OFF_MBAR + 0, 1);
        MBAR_INIT(sb + OFF_MBAR + 8, 1);
    }
    __syncthreads();
    if (tid == 0) {
        MBAR_EXPECT_TX(sb + OFF_MBAR + 0, CHUNK_BYTES);
        BULK_CP(sb + OFF_B, Wt, CHUNK_BYTES, sb + OFF_MBAR + 0);
    }

    // ---- x0 tile (4 batches, contiguous 2048 floats) + bias -> SMEM ----
    {
        const float* src = inputs + (size_t)blk * 2048;
        float* x0sw = reinterpret_cast<float*>(smem + OFF_X0);
#pragma unroll
        for (int i = 0; i < 8; i++) {
            int idx = tid + i * NTHR;
            int bb = idx >> 9, m = (idx >> 4) & 31, d = idx & 15;
            x0sw[(bb * 16 + d) * 33 + m] = src[idx];
        }
        if (tid < 128) reinterpret_cast<float*>(smem + OFF_BIAS)[tid] = bias[tid];
    }

    // ---- xl slice prologue (layers > 0): stage0 + prefetch chunk1 ----
    float* xls = reinterpret_cast<float*>(smem + OFF_XL);   // [2][4][64]
    const int xh = tid >> 6, xr = tid & 63;                 // this thread's slice elt
    float xlv = 0.f;
    if (LAYER > 0) {
        xls[tid] = __ldg(&xl_in[(size_t)xh * RTOT + R0 + xr]);      // chunk 0
        if (NC > 1) xlv = __ldg(&xl_in[(size_t)(4 + xh) * RTOT + R0 + xr]);
    }
    __syncthreads();   // x0s, bias, xl stage0 visible

    // ---- per-thread x0 fragment registers ----
    // rows rr = mg*32 + mt*16 + (lane>>2) + s*8  (mt,s in 0..1 -> idx mt*2+s)
    // m values per row: c0 + 8j + {0,1},  c0 = (lane&3)*2, j = 0..3
    const int mg = wid >> 2, ng = wid & 3;
    const int rlow = lane >> 2, c0 = (lane & 3) * 2;
    const int g = lane >> 3;
    const float* x0s = reinterpret_cast<const float*>(smem + OFF_X0);
    __half2 x0p[4][4];
    int rowv[4];
#pragma unroll
    for (int rr = 0; rr < 4; rr++) {
        const int mt = rr >> 1, s = rr & 1;
        const int row = mg * 32 + mt * 16 + rlow + s * 8;
        rowv[rr] = row;
#pragma unroll
        for (int j = 0; j < 4; j++)
            x0p[rr][j] = __floats2half2_rn(x0s[row * 33 + c0 + 8 * j],
                                           x0s[row * 33 + c0 + 8 * j + 1]);
    }

    // ---- accumulators: warp tile 32(M) x 32(N); warps = 2M x 4N ----
    float acc[2][4][4];
#pragma unroll
    for (int mt = 0; mt < 2; mt++)
#pragma unroll
        for (int nt = 0; nt < 4; nt++)
#pragma unroll
            for (int e = 0; e < 4; e++) acc[mt][nt][e] = 0.f;

    // ================= main K loop =================
    for (int c = 0; c < NC; c++) {
        const int sA = c & 1;

        MBAR_WAIT(sb + OFF_MBAR + 8 * sA, (c >> 1) & 1);  // B(c) landed
        __syncthreads();   // stage sA^1 consumed (c-1); xl stage (c&1) visible

        if (c + 1 < NC) {
            if (tid == 0) {
                MBAR_EXPECT_TX(sb + OFF_MBAR + 8 * (sA ^ 1), CHUNK_BYTES);
                BULK_CP(sb + OFF_B + (sA ^ 1) * 32768,
                        Wt + (size_t)(c + 1) * CHUNK_BYTES,
                        CHUNK_BYTES, sb + OFF_MBAR + 8 * (sA ^ 1));
            }
            if (LAYER > 0) {
                xls[((c + 1) & 1) * 256 + tid] = xlv;     // stage for c+1
                if (c + 2 < NC)
                    xlv = __ldg(&xl_in[(size_t)((c + 2) * 4 + xh) * RTOT + R0 + xr]);
            }
        }

        // ---- xl broadcast regs for this chunk: 4 rows x 4 h ----
        __half2 xl2[4][4];
#pragma unroll
        for (int rr = 0; rr < 4; rr++) {
#pragma unroll
            for (int hh = 0; hh < 4; hh++) {
                float v = (LAYER == 0)
                    ? x0s[rowv[rr] * 33 + c * 4 + hh]
                    : xls[(c & 1) * 256 + hh * 64 + rowv[rr]];
                xl2[rr][hh] = __half2half2(__float2half_rn(v));
            }
        }

        // ---- compute chunk c: 8 k16 steps; A built in registers ----
        const uint32_t bbase = sb + OFF_B + sA * 32768;
#pragma unroll
        for (int ks = 0; ks < 8; ks++) {
            const int k0 = ks * 16;
            const int hh = ks >> 1;
            const int jb = (ks & 1) * 2;
            uint32_t afr[2][4];
#pragma unroll
            for (int mt = 0; mt < 2; mt++) {
                afr[mt][0] = h2u(__hmul2(x0p[mt * 2 + 0][jb],     xl2[mt * 2 + 0][hh]));
                afr[mt][1] = h2u(__hmul2(x0p[mt * 2 + 1][jb],     xl2[mt * 2 + 1][hh]));
                afr[mt][2] = h2u(__hmul2(x0p[mt * 2 + 0][jb + 1], xl2[mt * 2 + 0][hh]));
                afr[mt][3] = h2u(__hmul2(x0p[mt * 2 + 1][jb + 1], xl2[mt * 2 + 1][hh]));
            }
            uint32_t bfr[4][2];
#pragma unroll
            for (int bt = 0; bt < 2; bt++) {
                const int br = ng * 32 + bt * 16 + (g >> 1) * 8 + (lane & 7);
                const int bk = k0 + (g & 1) * 8;
                uint32_t r[4];
                ldsm4(r, bbase + (bk >> 6) * 16384 + br * 128
                         + (((uint32_t)(bk & 63) * 2) ^ ((br & 7) << 4)));
                bfr[bt * 2][0] = r[0]; bfr[bt * 2][1] = r[1];
                bfr[bt * 2 + 1][0] = r[2]; bfr[bt * 2 + 1][1] = r[3];
            }
#pragma unroll
            for (int mt = 0; mt < 2; mt++)
#pragma unroll
                for (int nt = 0; nt < 4; nt++)
                    mma16816(acc[mt][nt], afr[mt], bfr[nt]);
        }
    }

    // ================= epilogue (disjoint 32x32 tiles) ======================
    const float* biass = reinterpret_cast<const float*>(smem + OFF_BIAS);
#pragma unroll
    for (int mt = 0; mt < 2; mt++) {
        const int batch = blk * 4 + mg * 2 + mt;     // one m16 tile == one batch
        const int r0 = R0 + mg * 32 + mt * 16 + rlow;
#pragma unroll
        for (int nt = 0; nt < 4; nt++) {
            const int j0 = ng * 32 + nt * 8 + (lane & 3) * 2;
            const float b0 = biass[j0], b1 = biass[j0 + 1];
            float v0 = acc[mt][nt][0] + b0;
            float v1 = acc[mt][nt][1] + b1;
            float v2 = acc[mt][nt][2] + b0;
            float v3 = acc[mt][nt][3] + b1;
            if (RELU) {
                v0 = fmaxf(v0, 0.f); v1 = fmaxf(v1, 0.f);
                v2 = fmaxf(v2, 0.f); v3 = fmaxf(v3, 0.f);
            }
            if (WXL) {
                xl_out[(size_t)j0 * RTOT + r0]           = v0;
                xl_out[(size_t)(j0 + 1) * RTOT + r0]     = v1;
                xl_out[(size_t)j0 * RTOT + r0 + 8]       = v2;
                xl_out[(size_t)(j0 + 1) * RTOT + r0 + 8] = v3;
            }
            float s0 = v0 + v2, s1 = v1 + v3;        // rows r, r+8
            s0 += __shfl_xor_sync(0xffffffffu, s0, 4);
            s1 += __shfl_xor_sync(0xffffffffu, s1, 4);
            s0 += __shfl_xor_sync(0xffffffffu, s0, 8);
            s1 += __shfl_xor_sync(0xffffffffu, s1, 8);
            s0 += __shfl_xor_sync(0xffffffffu, s0, 16);
            s1 += __shfl_xor_sync(0xffffffffu, s1, 16);
            if (lane < 4) {
                float* dst = out + (size_t)batch * OUTW + LAYER * NOUT
                           + ng * 32 + nt * 8 + lane * 2;
                dst[0] = s0;
                dst[1] = s1;
            }
        }
    }
}

// ---------------- host ----------------
extern "C" void kernel_launch(void* const* d_in, const int* in_sizes, int n_in,
                              void* d_out, int out_size)
{
    const float* inputs = (const float*)d_in[0];
    const float* W0     = (const float*)d_in[1];
    const float* b0     = (const float*)d_in[2];
    const float* W1     = (const float*)d_in[3];
    const float* b1     = (const float*)d_in[4];
    const float* W2     = (const float*)d_in[5];
    const float* b2     = (const float*)d_in[6];
    float* out = (float*)d_out;

    cudaFuncSetAttribute(cin_mma<0>, cudaFuncAttributeMaxDynamicSharedMemorySize, SMEM_TOTAL);
    cudaFuncSetAttribute(cin_mma<1>, cudaFuncAttributeMaxDynamicSharedMemorySize, SMEM_TOTAL);
    cudaFuncSetAttribute(cin_mma<2>, cudaFuncAttributeMaxDynamicSharedMemorySize, SMEM_TOTAL);

    wprep<0><<<32,  256>>>(W0);
    wprep<1><<<128, 256>>>(W1);
    wprep<2><<<128, 256>>>(W2);

    cin_mma<0><<<NCTA, NTHR, SMEM_TOTAL>>>(inputs, b0, out);
    cin_mma<1><<<NCTA, NTHR, SMEM_TOTAL>>>(inputs, b1, out);
    cin_mma<2><<<NCTA, NTHR, SMEM_TOTAL>>>(inputs, b2, out);
}